// round 17
// baseline (speedup 1.0000x reference)
#include <cuda_runtime.h>
#include <math.h>

// Problem constants
#define BB 64
#define SS 512
#define PD 300       // feature dim
#define KK 50        // labels
#define KP 64        // padded labels
#define RR 5
#define NROWS (BB*SS)        // 32768
#define BM 64                // rows per K1 block
#define XSS 300              // xs row stride in floats (1200B)
#define CH_ELEMS (150*KP*2)  // 19200 pair-packed chat floats (76800 B)
#define NCH 8                // k3 pooling chunks per batch

#define ROW_BYTES (PD*4)               // 1200
#define TOTAL_TX (CH_ELEMS*4 + BM*ROW_BYTES)   // 153600
#define CH_BYTES (CH_ELEMS*4)          // 76800

// Scratch (device globals; no runtime allocation allowed)
__device__ __align__(16) float g_inv[KP];           // label inverse norms
__device__ __align__(16) float g_chat2[CH_ELEMS];   // [pp=150][half=2][tx=16][q=4]
__device__ __align__(16) float g_G[NROWS*KK];       // [row][k] cosine scores
__device__ __align__(16) float g_beta[NROWS];       // softmax weights
__device__ __align__(16) float g_part[BB*NCH*PD];   // pooling partials

// ---- packed fp32x2 FMA (Blackwell FFMA2 path) ----
__device__ __forceinline__ void fma2(unsigned long long& d,
                                     unsigned long long a,
                                     unsigned long long b) {
    asm("fma.rn.f32x2 %0, %1, %2, %0;" : "+l"(d) : "l"(a), "l"(b));
}
__device__ __forceinline__ float sum2(unsigned long long v) {
    return __uint_as_float((unsigned)v) + __uint_as_float((unsigned)(v >> 32));
}
__device__ __forceinline__ unsigned s2u(const void* p) {
    unsigned a;
    asm("{ .reg .u64 t; cvta.to.shared.u64 t, %1; cvt.u32.u64 %0, t; }"
        : "=r"(a) : "l"(p));
    return a;
}
__device__ __forceinline__ void bulk_cp(unsigned dst, const void* src,
                                        unsigned bytes, unsigned mbar) {
    asm volatile(
        "cp.async.bulk.shared::cluster.global.mbarrier::complete_tx::bytes "
        "[%0], [%1], %2, [%3];"
        :: "r"(dst), "l"(src), "r"(bytes), "r"(mbar) : "memory");
}
__device__ __forceinline__ void mbar_wait(unsigned addr, unsigned parity) {
    asm volatile(
        "{\n\t.reg .pred P1;\n\t"
        "WAIT_%=: mbarrier.try_wait.parity.acquire.cta.shared::cta.b64 P1, [%0], %1, 0x989680;\n\t"
        "@P1 bra DONE_%=;\n\tbra WAIT_%=;\n\tDONE_%=:\n\t}"
        :: "r"(addr), "r"(parity) : "memory");
}
union F4U2 { float4 f; unsigned long long u[2]; };

// ============================================================
// K0a: label inverse norms -> g_inv. (k0 kept split so k1 stays
// the 4th launch inside the fixed ncu capture window)
// ============================================================
__global__ void k0a_norms(const float* __restrict__ C) {
    const int k = threadIdx.x;   // 64
    float v = 0.f;
    if (k < KK) {
        float s = 0.f;
        const float* row = C + k * PD;
        for (int p = 0; p < PD; p++) s = fmaf(row[p], row[p], s);
        v = 1.f / (sqrtf(s) + 0.001f);
    }
    g_inv[k] = v;
}

// ============================================================
// K0b/K0c: pack normalized C into g_chat2 (each does half).
// Per pp (512B row): half=0 holds k pairs {4tx, 4tx+1}, half=1 {4tx+2, 4tx+3}.
// ============================================================
__device__ __forceinline__ void pack_span(const float* C, int base, int span) {
    const int tid = threadIdx.x;
    for (int ii = blockIdx.x * 256 + tid; ii < span; ii += 512) {
        int i    = base + ii;
        int pp   = i >> 7;
        int rem  = i & 127;
        int half = rem >> 6;
        int w    = rem & 63;
        int tx   = w >> 2;
        int q    = w & 3;
        int k    = 4 * tx + 2 * half + (q >> 1);
        int e    = q & 1;
        int p    = 2 * pp + e;
        float v = 0.f;
        if (k < KK) v = C[k * PD + p] * g_inv[k];
        g_chat2[i] = v;
    }
}
__global__ void k0b_pack(const float* __restrict__ C) {
    pack_span(C, 0, CH_ELEMS / 2);
}
__global__ void k0c_pack(const float* __restrict__ C) {
    pack_span(C, CH_ELEMS / 2, CH_ELEMS / 2);
}

// ============================================================
// K1: gathered cosine-score GEMM, v6.
// Block: 64 rows x 64 k, 512 threads (16 warps = 4/SMSP: fixes the
// measured issue=43% starvation at 8 warps). Thread (tx,ty) computes
// 2 rows x 4 labels. Mainloop: unroll-by-2 ping-pong (NO rotation
// MOVs, fixing the measured alu=20% overhead).
// Staging via cp.async.bulk, chat + rows in smem (152 KB, occ 1).
// ============================================================
__global__ void __launch_bounds__(512, 1)
k1_scores(const int* __restrict__ idx, const float* __restrict__ emb) {
    extern __shared__ float sm1[];
    float* ch = sm1;                 // CH_ELEMS floats
    float* xs = sm1 + CH_ELEMS;      // BM * XSS floats
    __shared__ float inv[BM];
    __shared__ __align__(8) unsigned long long s_mbar;

    const int tid  = threadIdx.x;
    const int lane = tid & 31;
    const int warp = tid >> 5;       // 0..15
    const int row0 = blockIdx.x * BM;
    const unsigned mbar = s2u(&s_mbar);

    if (tid == 0)
        asm volatile("mbarrier.init.shared.b64 [%0], %1;"
                     :: "r"(mbar), "r"(1u) : "memory");
    __syncthreads();
    if (tid == 0)
        asm volatile("mbarrier.arrive.expect_tx.shared.b64 _, [%0], %1;"
                     :: "r"(mbar), "r"((unsigned)TOTAL_TX) : "memory");
    __syncthreads();

    // issue bulk copies: gather rows (tid<64) + chat chunks (tid 64..71)
    if (tid < BM) {
        const char* src = (const char*)(emb + (size_t)idx[row0 + tid] * PD);
        bulk_cp(s2u(xs + tid * XSS), src, ROW_BYTES, mbar);
    } else if (tid < BM + 8) {
        const int c = tid - BM;
        bulk_cp(s2u(ch) + (unsigned)c * (CH_BYTES / 8),
                (const char*)g_chat2 + c * (CH_BYTES / 8),
                CH_BYTES / 8, mbar);
    }
    mbar_wait(mbar, 0);
    __syncthreads();

    // inverse norms (warp per row; 16 warps x 4 rows)
    for (int r = warp; r < BM; r += 16) {
        const float* xr = xs + r * XSS;
        float ss = 0.f;
        #pragma unroll
        for (int i = 0; i < 10; i++) {
            int p = lane + 32 * i;
            if (p < PD) { float v = xr[p]; ss = fmaf(v, v, ss); }
        }
        #pragma unroll
        for (int o = 16; o; o >>= 1) ss += __shfl_xor_sync(0xffffffffu, ss, o);
        if (lane == 0) inv[r] = 1.f / (sqrtf(ss) + 0.001f);
    }
    __syncthreads();

    const int tx = tid & 15;   // 4 labels: k = 4tx..4tx+3
    const int ty = tid >> 4;   // 0..31: rows 2ty, 2ty+1

    unsigned long long acc[2][4];
    #pragma unroll
    for (int r = 0; r < 2; r++)
        #pragma unroll
        for (int c = 0; c < 4; c++) acc[r][c] = 0ull;

    const float* aBase = xs + (ty * 2) * XSS;
    const float* bBase = ch + tx * 4;   // 16B-stride chunks, conflict-free

    // ---- unroll-by-2 ping-pong mainloop over 75 units (2 pp each) ----
    F4U2 a0[2], a1[2];
    ulonglong2 b0[4], b1[4];

#define LOADU(as, bs, u) do {                                   \
        const float* ap_ = aBase + 4 * (u);                     \
        const float* bp_ = bBase + 256 * (u);                   \
        as[0].f = *(const float4*)(ap_);                        \
        as[1].f = *(const float4*)(ap_ + XSS);                  \
        bs[0] = *(const ulonglong2*)(bp_);                      \
        bs[1] = *(const ulonglong2*)(bp_ + 64);                 \
        bs[2] = *(const ulonglong2*)(bp_ + 128);                \
        bs[3] = *(const ulonglong2*)(bp_ + 192);                \
    } while (0)

#define COMPU(as, bs) do {                                      \
        _Pragma("unroll")                                       \
        for (int r_ = 0; r_ < 2; r_++) {                        \
            fma2(acc[r_][0], as[r_].u[0], bs[0].x);             \
            fma2(acc[r_][1], as[r_].u[0], bs[0].y);             \
            fma2(acc[r_][2], as[r_].u[0], bs[1].x);             \
            fma2(acc[r_][3], as[r_].u[0], bs[1].y);             \
            fma2(acc[r_][0], as[r_].u[1], bs[2].x);             \
            fma2(acc[r_][1], as[r_].u[1], bs[2].y);             \
            fma2(acc[r_][2], as[r_].u[1], bs[3].x);             \
            fma2(acc[r_][3], as[r_].u[1], bs[3].y);             \
        }                                                       \
    } while (0)

    LOADU(a0, b0, 0);
    #pragma unroll 1
    for (int u = 0; u < 74; u += 2) {
        LOADU(a1, b1, u + 1);
        COMPU(a0, b0);
        LOADU(a0, b0, u + 2);
        COMPU(a1, b1);
    }
    COMPU(a0, b0);   // unit 74

#undef LOADU
#undef COMPU

    // epilogue: scale by 1/(||x||+eps), store k<50
    #pragma unroll
    for (int r = 0; r < 2; r++) {
        const int lr = ty * 2 + r;
        const int row = row0 + lr;
        const float iv = inv[lr];
        float* gout = g_G + (size_t)row * KK;
        #pragma unroll
        for (int j = 0; j < 4; j++) {
            int k = tx * 4 + j;
            if (k < KK) gout[k] = sum2(acc[r][j]) * iv;
        }
    }
}

// ============================================================
// K2: per-batch conv(11) + relu + max-over-k + softmax over s.
// One block per b, 512 threads. Padded smem tile, stride 51.
// ============================================================
#define GST 51
#define GROWS (SS + 2*RR)   // 522

__global__ void __launch_bounds__(512, 1)
k2_attn(const float* __restrict__ cw, const float* __restrict__ cbp) {
    extern __shared__ float Gs[];   // GROWS * GST
    __shared__ float red1[16], red2[16];
    __shared__ float wloc[11];
    __shared__ float sc[3];         // [0]=conv_b, [1]=max, [2]=sum

    const int b = blockIdx.x, tid = threadIdx.x;
    if (tid < 11) wloc[tid] = cw[tid];
    if (tid == 16) sc[0] = cbp[0];

    for (int i = tid; i < RR * GST; i += 512) {
        Gs[i] = 0.f;
        Gs[(SS + RR) * GST + i] = 0.f;
    }
    const float* Gb = g_G + (size_t)b * SS * KK;
    for (int i = tid; i < SS * KK; i += 512) {
        int s = i / KK, k = i - s * KK;
        Gs[(s + RR) * GST + k] = Gb[i];
    }
    __syncthreads();

    const int s = tid;
    const float cbv = sc[0];
    float m = 0.f;   // relu >= 0
    for (int k = 0; k < KK; k++) {
        float v = cbv;
        const float* gp = Gs + s * GST + k;
        #pragma unroll
        for (int j = 0; j < 11; j++) v = fmaf(wloc[j], gp[j * GST], v);
        m = fmaxf(m, fmaxf(v, 0.f));
    }

    const int lane = tid & 31, warp = tid >> 5;
    float mx = m;
    #pragma unroll
    for (int o = 16; o; o >>= 1) mx = fmaxf(mx, __shfl_xor_sync(0xffffffffu, mx, o));
    if (lane == 0) red1[warp] = mx;
    __syncthreads();
    if (warp == 0) {
        float v = (lane < 16) ? red1[lane] : -1e30f;
        #pragma unroll
        for (int o = 8; o; o >>= 1) v = fmaxf(v, __shfl_xor_sync(0xffffffffu, v, o));
        if (lane == 0) sc[1] = v;
    }
    __syncthreads();
    float e = expf(m - sc[1]);
    float sum = e;
    #pragma unroll
    for (int o = 16; o; o >>= 1) sum += __shfl_xor_sync(0xffffffffu, sum, o);
    if (lane == 0) red2[warp] = sum;
    __syncthreads();
    if (warp == 0) {
        float v = (lane < 16) ? red2[lane] : 0.f;
        #pragma unroll
        for (int o = 8; o; o >>= 1) v += __shfl_xor_sync(0xffffffffu, v, o);
        if (lane == 0) sc[2] = v;
    }
    __syncthreads();
    g_beta[b * SS + s] = e / sc[2];
}

// ============================================================
// K3a: pooling partials. grid (8 chunks, 64 b), 320 threads,
// 64 s per block (measured-best config).
// ============================================================
__global__ void __launch_bounds__(320, 1)
k3a_pool(const int* __restrict__ idx, const float* __restrict__ emb) {
    __shared__ float sbeta[64];
    __shared__ int   sidx[64];
    const int cx = blockIdx.x, b = blockIdx.y, tid = threadIdx.x;
    const int s0 = b * SS + cx * 64;
    if (tid < 64) {
        sbeta[tid] = g_beta[s0 + tid];
        sidx[tid]  = idx[s0 + tid];
    }
    __syncthreads();
    if (tid < PD) {
        float a0 = 0.f, a1 = 0.f, a2 = 0.f, a3 = 0.f;
        #pragma unroll 4
        for (int s = 0; s < 64; s += 4) {
            a0 = fmaf(sbeta[s],     emb[(size_t)sidx[s]     * PD + tid], a0);
            a1 = fmaf(sbeta[s + 1], emb[(size_t)sidx[s + 1] * PD + tid], a1);
            a2 = fmaf(sbeta[s + 2], emb[(size_t)sidx[s + 2] * PD + tid], a2);
            a3 = fmaf(sbeta[s + 3], emb[(size_t)sidx[s + 3] * PD + tid], a3);
        }
        g_part[(b * NCH + cx) * PD + tid] = (a0 + a1) + (a2 + a3);
    }
}

// ============================================================
// K3b: combine partials + final GEMV out = pooled @ W2^T + b2.
// ============================================================
__global__ void __launch_bounds__(320, 4)
k3b_out(const float* __restrict__ W2, const float* __restrict__ b2,
        float* __restrict__ out) {
    __shared__ float pooled[PD];
    const int b = blockIdx.x, tid = threadIdx.x;
    if (tid < PD) {
        float s = 0.f;
        #pragma unroll
        for (int c = 0; c < NCH; c++) s += g_part[(b * NCH + c) * PD + tid];
        pooled[tid] = s * (1.0f / (float)SS);
    }
    __syncthreads();

    const int warp = tid >> 5, lane = tid & 31;  // 10 warps x 5 k
    #pragma unroll
    for (int kk = 0; kk < 5; kk++) {
        int k = warp * 5 + kk;
        float d = 0.f;
        for (int p = lane; p < PD; p += 32) d = fmaf(pooled[p], W2[k * PD + p], d);
        #pragma unroll
        for (int o = 16; o; o >>= 1) d += __shfl_xor_sync(0xffffffffu, d, o);
        if (lane == 0) out[b * KK + k] = d + b2[k];
    }
}

// ============================================================
extern "C" void kernel_launch(void* const* d_in, const int* in_sizes, int n_in,
                              void* d_out, int out_size) {
    const int*   idx    = (const int*)d_in[0];
    const float* emb    = (const float*)d_in[1];
    const float* C      = (const float*)d_in[2];
    const float* conv_w = (const float*)d_in[3];
    const float* conv_b = (const float*)d_in[4];
    const float* W2     = (const float*)d_in[5];
    const float* b2     = (const float*)d_in[6];
    float*       out    = (float*)d_out;

    const int sm1 = (CH_ELEMS + BM * XSS) * (int)sizeof(float);   // ~152 KB
    const int sm2 = GROWS * GST * (int)sizeof(float);             // ~106 KB
    cudaFuncSetAttribute(k1_scores, cudaFuncAttributeMaxDynamicSharedMemorySize, sm1);
    cudaFuncSetAttribute(k2_attn,   cudaFuncAttributeMaxDynamicSharedMemorySize, sm2);

    // k1 deliberately stays the 4th launch for the fixed ncu window.
    k0a_norms<<<1, 64>>>(C);
    k0b_pack<<<2, 256>>>(C);
    k0c_pack<<<2, 256>>>(C);
    k1_scores<<<NROWS / BM, 512, sm1>>>(idx, emb);
    k2_attn<<<BB, 512, sm2>>>(conv_w, conv_b);
    k3a_pool<<<dim3(NCH, BB), 320>>>(idx, emb);
    k3b_out<<<BB, 320>>>(W2, b2, out);
}